// round 10
// baseline (speedup 1.0000x reference)
#include <cuda_runtime.h>
#include <cstdint>

// NodeDropout: out[e] = values[e] * keep[src[e]] * keep[dst[e]],  keep[i] = !nodes_flag[i]
//
// Layout (pinned by R4-R6 evidence on this bench):
//   d_in[0] : edge_index  (2, E) row-major, int32
//   d_in[1] : values      float32, E
//   d_in[2] : nodes_flag  N x 4-byte words (nonzero = dropped)
// Output: float32, E.
//
// K1: pack flag words -> 122 KB keep-bitmask (__device__ global).
// K2: 1 CTA/SM (dyn smem = bitmask), bitmask staged in shared memory; grid-stride
//     over 8 contiguous edges per thread per iteration, all-int32 indexing,
//     128-bit loads/stores. Flag gathers are random LDS.

#define MAX_BIT_WORDS 32768   // up to 1,048,576 nodes

__device__ uint32_t g_keep_bits[MAX_BIT_WORDS];

// ---------------------------------------------------------------------------
// K1: pack 4-byte flags -> keep bitmask (bit = 1 means node is KEPT)
// ---------------------------------------------------------------------------
__global__ void pack_flags_kernel(const uint32_t* __restrict__ flags,
                                  int n_nodes, int n_words) {
    int t = blockIdx.x * blockDim.x + threadIdx.x;
    if (t >= n_words) return;

    const int base = t * 32;
    uint32_t  w    = 0;

    if (base + 32 <= n_nodes) {
        const uint4* p = reinterpret_cast<const uint4*>(flags + base);  // 128 B
#pragma unroll
        for (int c = 0; c < 8; c++) {
            uint4 q = p[c];
            w |= (q.x ? 0u : 1u) << (c * 4 + 0);
            w |= (q.y ? 0u : 1u) << (c * 4 + 1);
            w |= (q.z ? 0u : 1u) << (c * 4 + 2);
            w |= (q.w ? 0u : 1u) << (c * 4 + 3);
        }
    } else {
        int lim = n_nodes - base;
        for (int j = 0; j < 32; j++) {
            uint32_t fv = (j < lim) ? flags[base + j] : 1u;  // OOB = dropped
            w |= (fv ? 0u : 1u) << j;
        }
    }
    g_keep_bits[t] = w;
}

// ---------------------------------------------------------------------------
// K2: masked edge scaling with smem-resident bitmask
// ---------------------------------------------------------------------------
__device__ __forceinline__ uint32_t keep2(const uint32_t* __restrict__ s_bits,
                                          uint32_t s, uint32_t d) {
    return (s_bits[s >> 5] >> (s & 31)) & (s_bits[d >> 5] >> (d & 31)) & 1u;
}

__global__ __launch_bounds__(1024, 1)
void node_dropout_kernel(const int* __restrict__ ei,
                         const float* __restrict__ vals,
                         float* __restrict__ out,
                         int E, int n_words) {
    extern __shared__ uint32_t s_bits[];

    // Stage bitmask (coalesced; L2-hot right after pack kernel).
    for (int i = threadIdx.x; i < n_words; i += blockDim.x)
        s_bits[i] = g_keep_bits[i];
    __syncthreads();

    const int* __restrict__ src = ei;
    const int* __restrict__ dst = ei + E;

    const int octs   = E >> 3;                       // 8 edges per iteration
    const int stride = gridDim.x * blockDim.x;       // fits in int
    int       i      = blockIdx.x * blockDim.x + threadIdx.x;

    for (; i < octs; i += stride) {
        const int e = i << 3;

        // Front-load 8 independent 128-bit global reads.
        int4   s0 = *reinterpret_cast<const int4*>(src + e);
        int4   s1 = *reinterpret_cast<const int4*>(src + e + 4);
        int4   d0 = *reinterpret_cast<const int4*>(dst + e);
        int4   d1 = *reinterpret_cast<const int4*>(dst + e + 4);
        float4 v0 = *reinterpret_cast<const float4*>(vals + e);
        float4 v1 = *reinterpret_cast<const float4*>(vals + e + 4);

        // Random LDS gathers (bank conflicts ~4-way, hidden under HBM).
        uint32_t k0 = keep2(s_bits, (uint32_t)s0.x, (uint32_t)d0.x);
        uint32_t k1 = keep2(s_bits, (uint32_t)s0.y, (uint32_t)d0.y);
        uint32_t k2 = keep2(s_bits, (uint32_t)s0.z, (uint32_t)d0.z);
        uint32_t k3 = keep2(s_bits, (uint32_t)s0.w, (uint32_t)d0.w);
        uint32_t k4 = keep2(s_bits, (uint32_t)s1.x, (uint32_t)d1.x);
        uint32_t k5 = keep2(s_bits, (uint32_t)s1.y, (uint32_t)d1.y);
        uint32_t k6 = keep2(s_bits, (uint32_t)s1.z, (uint32_t)d1.z);
        uint32_t k7 = keep2(s_bits, (uint32_t)s1.w, (uint32_t)d1.w);

        float4 o0, o1;
        o0.x = k0 ? v0.x : 0.0f;
        o0.y = k1 ? v0.y : 0.0f;
        o0.z = k2 ? v0.z : 0.0f;
        o0.w = k3 ? v0.w : 0.0f;
        o1.x = k4 ? v1.x : 0.0f;
        o1.y = k5 ? v1.y : 0.0f;
        o1.z = k6 ? v1.z : 0.0f;
        o1.w = k7 ? v1.w : 0.0f;

        *reinterpret_cast<float4*>(out + e)     = o0;
        *reinterpret_cast<float4*>(out + e + 4) = o1;
    }

    // Tail edges (E % 8).
    int gtid = blockIdx.x * blockDim.x + threadIdx.x;
    int e = (octs << 3) + gtid;
    if (e < E) {
        uint32_t k = keep2(s_bits, (uint32_t)src[e], (uint32_t)dst[e]);
        out[e] = k ? vals[e] : 0.0f;
    }
}

// ---------------------------------------------------------------------------
// Launch
// ---------------------------------------------------------------------------
extern "C" void kernel_launch(void* const* d_in, const int* in_sizes, int n_in,
                              void* d_out, int out_size) {
    const int*      ei    = (const int*)d_in[0];
    const float*    vals  = (const float*)d_in[1];
    const uint32_t* flags = (const uint32_t*)d_in[2];
    float*          out   = (float*)d_out;

    const int E       = in_sizes[0] / 2;
    const int n_nodes = in_sizes[2];
    const int n_words = (n_nodes + 31) / 32;

    // K1: pack flags into keep-bitmask
    {
        int threads = 256;
        int blocks  = (n_words + threads - 1) / threads;
        pack_flags_kernel<<<blocks, threads>>>(flags, n_nodes, n_words);
    }

    // K2: masked scaling with smem bitmask
    {
        int sm_count = 148;
        cudaDeviceGetAttribute(&sm_count, cudaDevAttrMultiProcessorCount, 0);

        size_t smem_bytes = (size_t)n_words * sizeof(uint32_t);
        cudaFuncSetAttribute(node_dropout_kernel,
                             cudaFuncAttributeMaxDynamicSharedMemorySize,
                             (int)smem_bytes);

        node_dropout_kernel<<<sm_count, 1024, smem_bytes>>>(ei, vals, out, E, n_words);
    }
}